// round 3
// baseline (speedup 1.0000x reference)
#include <cuda_runtime.h>
#include <cstdint>

// Problem constants
#define BB 8
#define CC 512
#define OO 512
#define HH 32
#define WW 32
#define KTOT 2048   // CC * 4 taps
#define KC 32       // K chunk staged in smem

// Scratch (no allocation allowed -> device globals)
__device__ float g_smod[BB * CC];          // 1 + style @ fc_w^T + fc_b
__device__ float g_d[BB * OO];             // demod scale
__device__ float g_w2t[CC * OO];           // sum_k conv_w^2, transposed [c][o]
__device__ float g_weff[4 * KTOT * OO];    // parity-combined 2x2 weights [p][k][o]

// ---------------------------------------------------------------------------
// s[b][c] = 1 + fc_b[c] + sum_k style[b][k] * fc_w[c][k]
// grid: (8), block: 512
__global__ void k_style(const float* __restrict__ style,
                        const float* __restrict__ fc_w,
                        const float* __restrict__ fc_b) {
    __shared__ float ss[512];
    int b = blockIdx.x;
    int c = threadIdx.x;
    ss[c] = style[b * 512 + c];
    __syncthreads();
    const float4* wrow = (const float4*)(fc_w + (size_t)c * 512);
    float acc = 0.f;
#pragma unroll 4
    for (int k = 0; k < 128; k++) {
        float4 w4 = wrow[k];
        acc += w4.x * ss[4 * k + 0] + w4.y * ss[4 * k + 1]
             + w4.z * ss[4 * k + 2] + w4.w * ss[4 * k + 3];
    }
    g_smod[b * 512 + c] = acc + fc_b[c] + 1.0f;
}

// ---------------------------------------------------------------------------
// Per (o,c): W2^T and the 4-parity combined 2x2 stencil weights.
// Parity py: even output rows use input rows {y-1 (w0), y (w1+w2)};
//            odd  output rows use input rows {y (w0+w1), y+1 (w2)}. Same in x.
// Layout g_weff[p][k][o], k = c*4 + j*2 + i (j row tap, i col tap).
// grid: 1024 blocks x 256
__global__ void k_weff(const float* __restrict__ conv_w) {
    int t = blockIdx.x * 256 + threadIdx.x;   // 262144 threads
    int o = t & 511;
    int c = t >> 9;
    const float* wp = conv_w + ((size_t)o * 512 + c) * 9;
    float w[9];
    float s2 = 0.f;
#pragma unroll
    for (int q = 0; q < 9; q++) { w[q] = wp[q]; s2 += w[q] * w[q]; }
    g_w2t[c * 512 + o] = s2;

#pragma unroll
    for (int py = 0; py < 2; py++) {
        float r0[3], r1[3];   // row-combined weights for j=0 / j=1
#pragma unroll
        for (int kx = 0; kx < 3; kx++) {
            r0[kx] = (py == 0) ? w[kx]            : w[kx] + w[3 + kx];
            r1[kx] = (py == 0) ? w[3 + kx] + w[6 + kx] : w[6 + kx];
        }
#pragma unroll
        for (int px = 0; px < 2; px++) {
            float v00 = (px == 0) ? r0[0] : r0[0] + r0[1];
            float v01 = (px == 0) ? r0[1] + r0[2] : r0[2];
            float v10 = (px == 0) ? r1[0] : r1[0] + r1[1];
            float v11 = (px == 0) ? r1[1] + r1[2] : r1[2];
            int p = py * 2 + px;
            size_t base = ((size_t)p * KTOT + c * 4) * 512 + o;
            g_weff[base]        = v00;  // j=0,i=0
            g_weff[base + 512]  = v01;  // j=0,i=1
            g_weff[base + 1024] = v10;  // j=1,i=0
            g_weff[base + 1536] = v11;  // j=1,i=1
        }
    }
}

// ---------------------------------------------------------------------------
// d[b][o] = rsqrt( sum_c smod[b][c]^2 * W2[o][c] + 1e-8 )
// grid: (2, 8), block 256
__global__ void k_demod() {
    __shared__ float s2[512];
    int b = blockIdx.y;
    int o = blockIdx.x * 256 + threadIdx.x;
    {
        float a = g_smod[b * 512 + threadIdx.x];
        float bv = g_smod[b * 512 + threadIdx.x + 256];
        s2[threadIdx.x] = a * a;
        s2[threadIdx.x + 256] = bv * bv;
    }
    __syncthreads();
    float acc = 1e-8f;
#pragma unroll 4
    for (int c = 0; c < 512; c++)
        acc += s2[c] * g_w2t[c * 512 + o];
    g_d[b * 512 + o] = rsqrtf(acc);
}

// ---------------------------------------------------------------------------
// Implicit GEMM conv: per (b, parity): out[o][n] = sum_k Weff[p][k][o]*Xg[k][n]
// Block: 64 o x 128 n tile, 256 threads, 8x4 register tile per thread.
// grid: (8 n-tiles, 8 o-tiles, 32 = b*4+p)
__global__ void __launch_bounds__(256) k_conv(const float* __restrict__ x,
                                              const float* __restrict__ noise,
                                              const float* __restrict__ bias,
                                              float* __restrict__ out) {
    __shared__ float Ws[KC][64];
    __shared__ float Xs[KC][128];
    __shared__ float smod_s[512];

    int bz = blockIdx.z;
    int b  = bz >> 2;
    int p  = bz & 3;
    int py = p >> 1, px = p & 1;
    int obase = blockIdx.y * 64;
    int nbase = blockIdx.x * 128;
    int tid = threadIdx.x;
    int to = tid >> 5;        // warp id -> o sub-tile
    int tn = tid & 31;        // lane    -> n sub-tile

    smod_s[tid]       = g_smod[b * 512 + tid];
    smod_s[tid + 256] = g_smod[b * 512 + tid + 256];

    // ---- x-loader thread constants: fixed pixel nn, two alternating taps ----
    int nn  = tid & 127;      // pixel within tile
    int kl0 = tid >> 7;       // 0/1: kk = kl0 + 2*pass
    int n0 = nbase + nn;
    int yb = n0 >> 5, xb0 = n0 & 31;
    // tapA = kl0 -> (j=0, i=kl0), tapB = kl0+2 -> (j=1, i=kl0); i identical.
    int xx  = xb0 + (kl0)-1 + px;
    int yyA = yb - 1 + py;
    int yyB = yb + py;
    bool vx = (unsigned)xx < 32u;
    bool vA = vx && ((unsigned)yyA < 32u);
    bool vB = vx && ((unsigned)yyB < 32u);
    int offA = yyA * 32 + xx;
    int offB = yyB * 32 + xx;
    const float* xbp = x + (size_t)b * 512 * 1024;

    // ---- weight-loader constants ----
    int woo = tid & 63;
    int wk0 = tid >> 6;       // 0..3: kk = wk0 + 4*pass
    const float* wg = g_weff + (size_t)p * KTOT * 512 + obase;

    float acc[8][4];
#pragma unroll
    for (int q = 0; q < 8; q++)
#pragma unroll
        for (int r = 0; r < 4; r++) acc[q][r] = 0.f;

    __syncthreads();  // smod_s ready

    for (int k0 = 0; k0 < KTOT; k0 += KC) {
        int c0 = k0 >> 2;
        // stage weights
#pragma unroll
        for (int ps = 0; ps < 8; ps++) {
            int kk = wk0 + 4 * ps;
            Ws[kk][woo] = wg[(size_t)(k0 + kk) * 512 + woo];
        }
        // stage gathered inputs (modulated)
#pragma unroll
        for (int ps = 0; ps < 16; ps++) {
            int kk = kl0 + 2 * ps;
            int c  = c0 + (ps >> 1);
            float sv = smod_s[c];
            float v;
            if ((ps & 1) == 0) v = vA ? xbp[c * 1024 + offA] * sv : 0.f;
            else               v = vB ? xbp[c * 1024 + offB] * sv : 0.f;
            Xs[kk][nn] = v;
        }
        __syncthreads();
#pragma unroll
        for (int kk = 0; kk < KC; kk++) {
            float4 xa = *(const float4*)&Xs[kk][tn * 4];
            float4 wa = *(const float4*)&Ws[kk][to * 8];
            float4 wb = *(const float4*)&Ws[kk][to * 8 + 4];
            float wq[8] = {wa.x, wa.y, wa.z, wa.w, wb.x, wb.y, wb.z, wb.w};
            float xr[4] = {xa.x, xa.y, xa.z, xa.w};
#pragma unroll
            for (int q = 0; q < 8; q++)
#pragma unroll
                for (int r = 0; r < 4; r++)
                    acc[q][r] += wq[q] * xr[r];
        }
        __syncthreads();
    }

    // ---- epilogue: demod scale + bias + noise + leaky ----
#pragma unroll
    for (int q = 0; q < 8; q++) {
        int o  = obase + to * 8 + q;
        float dv = g_d[b * 512 + o];
        float bv = bias[o];
#pragma unroll
        for (int r = 0; r < 4; r++) {
            int n = nbase + tn * 4 + r;
            int y = n >> 5, xq = n & 31;
            int oy = 2 * y + py, ox = 2 * xq + px;
            float v = acc[q][r] * dv + bv + noise[b * 4096 + oy * 64 + ox];
            v = (v >= 0.f) ? v : 0.2f * v;
            out[(((size_t)b * 512 + o) * 64 + oy) * 64 + ox] = v;
        }
    }
}

// ---------------------------------------------------------------------------
extern "C" void kernel_launch(void* const* d_in, const int* in_sizes, int n_in,
                              void* d_out, int out_size) {
    const float* x      = (const float*)d_in[0];
    const float* style  = (const float*)d_in[1];
    const float* noise  = (const float*)d_in[2];
    const float* conv_w = (const float*)d_in[3];
    const float* fc_w   = (const float*)d_in[4];
    const float* fc_b   = (const float*)d_in[5];
    const float* bias   = (const float*)d_in[6];
    float* out = (float*)d_out;

    k_style<<<8, 512>>>(style, fc_w, fc_b);
    k_weff<<<1024, 256>>>(conv_w);
    k_demod<<<dim3(2, 8), 256>>>();
    k_conv<<<dim3(8, 8, 32), 256>>>(x, noise, bias, out);
}

// round 7
// speedup vs baseline: 4.2045x; 4.2045x over previous
#include <cuda_runtime.h>
#include <cuda_fp16.h>
#include <cstdint>

// Problem constants
#define BB 8
#define CC 512
#define OO 512
#define KTOT 2048          // CC * 4 taps
#define KC 32              // K per chunk
#define NCHUNKS 64         // KTOT / KC
#define LDR 80             // smem row stride (bytes): 64B data + 16B pad (conflict-free ldmatrix)

// Scratch (no allocation allowed -> device globals)
__device__ float g_smod[BB * CC];                    // 1 + style @ fc_w^T + fc_b
__device__ float g_d[BB * OO];                       // demod scale
__device__ float g_w2t[CC * OO];                     // sum_k conv_w^2, [c][o]
__device__ __align__(16) __half g_wh[4 * OO * KTOT]; // [p][o][k] fp16 parity weights
__device__ __align__(16) __half g_xs[BB * CC * 1024];// fp16(x * smod) [b][c][pix]

// ---------------------------------------------------------------------------
__device__ __forceinline__ uint32_t smem_u32(const void* p) {
    uint32_t a;
    asm("{ .reg .u64 t; cvta.to.shared.u64 t, %1; cvt.u32.u64 %0, t; }"
        : "=r"(a) : "l"(p));
    return a;
}
#define CP_ASYNC16(dst, src) \
    asm volatile("cp.async.cg.shared.global [%0], [%1], 16;\n" \
                 :: "r"(dst), "l"(__cvta_generic_to_global(src)))
#define CP_COMMIT()  asm volatile("cp.async.commit_group;\n" ::: "memory")
#define CP_WAIT1()   asm volatile("cp.async.wait_group 1;\n" ::: "memory")

#define LDMATRIX_X4(r, addr) \
    asm volatile("ldmatrix.sync.aligned.m8n8.x4.shared.b16 {%0,%1,%2,%3}, [%4];\n" \
                 : "=r"((r)[0]), "=r"((r)[1]), "=r"((r)[2]), "=r"((r)[3]) : "r"(addr))

#define MMA16816(d, a, b0v, b1v) \
    asm volatile("mma.sync.aligned.m16n8k16.row.col.f32.f16.f16.f32 " \
                 "{%0,%1,%2,%3},{%4,%5,%6,%7},{%8,%9},{%0,%1,%2,%3};\n" \
                 : "+f"((d)[0]), "+f"((d)[1]), "+f"((d)[2]), "+f"((d)[3]) \
                 : "r"((a)[0]), "r"((a)[1]), "r"((a)[2]), "r"((a)[3]), \
                   "r"(b0v), "r"(b1v))

// ---------------------------------------------------------------------------
// s[b][c] = 1 + fc_b[c] + sum_k style[b][k] * fc_w[c][k]
__global__ void k_style(const float* __restrict__ style,
                        const float* __restrict__ fc_w,
                        const float* __restrict__ fc_b) {
    __shared__ float ss[512];
    int b = blockIdx.x;
    int c = threadIdx.x;
    ss[c] = style[b * 512 + c];
    __syncthreads();
    const float4* wrow = (const float4*)(fc_w + (size_t)c * 512);
    float acc = 0.f;
#pragma unroll 4
    for (int k = 0; k < 128; k++) {
        float4 w4 = wrow[k];
        acc += w4.x * ss[4 * k + 0] + w4.y * ss[4 * k + 1]
             + w4.z * ss[4 * k + 2] + w4.w * ss[4 * k + 3];
    }
    g_smod[b * 512 + c] = acc + fc_b[c] + 1.0f;
}

// ---------------------------------------------------------------------------
// Per (o,c): W2^T and 4-parity combined 2x2 stencil weights (fp16).
// Layout g_wh: [p][o][k], k = c*4 + j*2 + i.
__global__ void k_weff(const float* __restrict__ conv_w) {
    int t = blockIdx.x * 256 + threadIdx.x;   // 262144 threads
    int o = t & 511;
    int c = t >> 9;
    const float* wp = conv_w + ((size_t)o * 512 + c) * 9;
    float w[9];
    float s2 = 0.f;
#pragma unroll
    for (int q = 0; q < 9; q++) { w[q] = wp[q]; s2 += w[q] * w[q]; }
    g_w2t[c * 512 + o] = s2;

#pragma unroll
    for (int py = 0; py < 2; py++) {
        float r0[3], r1[3];
#pragma unroll
        for (int kx = 0; kx < 3; kx++) {
            r0[kx] = (py == 0) ? w[kx]                 : w[kx] + w[3 + kx];
            r1[kx] = (py == 0) ? w[3 + kx] + w[6 + kx] : w[6 + kx];
        }
#pragma unroll
        for (int px = 0; px < 2; px++) {
            float v[4];
            v[0] = (px == 0) ? r0[0] : r0[0] + r0[1];
            v[1] = (px == 0) ? r0[1] + r0[2] : r0[2];
            v[2] = (px == 0) ? r1[0] : r1[0] + r1[1];
            v[3] = (px == 0) ? r1[1] + r1[2] : r1[2];
            int p = py * 2 + px;
            size_t kb = ((size_t)p * 512 + o) * 2048 + c * 4;
#pragma unroll
            for (int tap = 0; tap < 4; tap++)
                g_wh[kb + tap] = __float2half_rn(v[tap]);
        }
    }
}

// ---------------------------------------------------------------------------
// d[b][o] = rsqrt( sum_c smod[b][c]^2 * W2[o][c] + 1e-8 )
__global__ void k_demod() {
    __shared__ float s2[512];
    int b = blockIdx.y;
    int o = blockIdx.x * 256 + threadIdx.x;
    {
        float a = g_smod[b * 512 + threadIdx.x];
        float bv = g_smod[b * 512 + threadIdx.x + 256];
        s2[threadIdx.x] = a * a;
        s2[threadIdx.x + 256] = bv * bv;
    }
    __syncthreads();
    float acc = 1e-8f;
#pragma unroll 4
    for (int c = 0; c < 512; c++)
        acc += s2[c] * g_w2t[c * 512 + o];
    g_d[b * 512 + o] = rsqrtf(acc);
}

// ---------------------------------------------------------------------------
// xs[b][c][pix] = fp16( x[b][c][pix] * smod[b][c] ), float4-vectorized
// grid 4096 x 256
__global__ void k_xsplit(const float* __restrict__ x) {
    int i = blockIdx.x * 256 + threadIdx.x;      // 1,048,576 threads
    int e0 = i * 4;
    int b = e0 >> 19;
    int c = (e0 >> 10) & 511;
    float s = g_smod[b * 512 + c];
    float4 v = *(const float4*)(x + e0);
    __half2 h0 = __floats2half2_rn(v.x * s, v.y * s);
    __half2 h1 = __floats2half2_rn(v.z * s, v.w * s);
    uint2 pk;
    pk.x = *(uint32_t*)&h0;
    pk.y = *(uint32_t*)&h1;
    *(uint2*)((char*)g_xs + (size_t)e0 * 2) = pk;
}

// ---------------------------------------------------------------------------
// Tensor-core implicit-GEMM conv via mma.sync (fp16 in, fp32 acc):
// per (b,p): D[o][n] = sum_k Weff[o][k] * Xg[n][k]
// CTA tile 128o x 128n, KC=32 double-buffered, cp.async W feed, gathered X.
// smem: buf0 W@0 X@10240, buf1 W@20480 X@30720; epilogue Ds[128][132] @0.
#define SMEM_REQ 67584

__global__ void __launch_bounds__(256, 2) k_mma(const float* __restrict__ noise,
                                                const float* __restrict__ bias,
                                                float* __restrict__ out) {
    extern __shared__ __align__(16) char smem_raw[];
    char* abase = smem_raw;
    uint32_t base = smem_u32(smem_raw);

    const int tid = threadIdx.x;
    const int wid = tid >> 5;
    const int lane = tid & 31;

    int bz = blockIdx.z;
    int b = bz >> 2, p = bz & 3;
    int py = p >> 1, px = p & 1;
    int obase = blockIdx.y * 128;
    int nbase = blockIdx.x * 128;
    int ybase4 = blockIdx.x * 4;

    // ---- gather thread constants ----
    const int nn = tid & 127;        // X-tile row (n local)
    const int khalf = tid >> 7;      // 0/1
    int yb = ybase4 + (nn >> 5);
    int xb = nn & 31;
    int offt[4];
    unsigned vt[4];
#pragma unroll
    for (int j = 0; j < 2; j++)
#pragma unroll
        for (int i = 0; i < 2; i++) {
            int tap = j * 2 + i;
            int yy = yb + j - 1 + py;
            int xx = xb + i - 1 + px;
            vt[tap] = ((unsigned)yy < 32u) && ((unsigned)xx < 32u);
            offt[tap] = yy * 32 + xx;
        }

    // ---- stage lambda ----
    auto stage = [&](int kc, int bf) {
        uint32_t wdst = base + bf * 20480;
        // W: 128 rows x 64B via cp.async (2 x 16B per thread)
#pragma unroll
        for (int s = 0; s < 2; s++) {
            int opid = tid + 256 * s;
            int row = opid >> 2, seg = opid & 3;
            const __half* src = g_wh + ((size_t)(p * 512 + obase + row)) * 2048
                              + kc * 32 + seg * 8;
            CP_ASYNC16(wdst + row * LDR + seg * 16, src);
        }
        // X: gather 4 taps per (n, c), 4 c's per thread
        char* xdst = abase + bf * 20480 + 10240;
#pragma unroll
        for (int q = 0; q < 4; q++) {
            int cl = khalf + 2 * q;
            int c = kc * 8 + cl;
            const unsigned short* xc =
                (const unsigned short*)g_xs + (((size_t)b * 512 + c) << 10);
            unsigned u0 = vt[0] ? (unsigned)xc[offt[0]] : 0u;
            unsigned u1 = vt[1] ? (unsigned)xc[offt[1]] : 0u;
            unsigned u2 = vt[2] ? (unsigned)xc[offt[2]] : 0u;
            unsigned u3 = vt[3] ? (unsigned)xc[offt[3]] : 0u;
            *(uint2*)(xdst + nn * LDR + cl * 8) =
                make_uint2(u0 | (u1 << 16), u2 | (u3 << 16));
        }
    };

    // ---- warp tile constants ----
    const int moff = (wid & 1) * 64;
    const int noff = (wid >> 1) * 32;
    const uint32_t aoff = (uint32_t)((moff + (lane & 15)) * LDR + ((lane >> 4) * 8) * 2);
    const uint32_t boff = (uint32_t)((noff + (lane & 7) + ((lane >> 4) << 3)) * LDR
                                     + (((lane >> 3) & 1) * 8) * 2);

    float acc[16][4];
#pragma unroll
    for (int q = 0; q < 16; q++)
#pragma unroll
        for (int r = 0; r < 4; r++) acc[q][r] = 0.f;

    // ---- prologue ----
    stage(0, 0); CP_COMMIT();
    stage(1, 1); CP_COMMIT();

    // ---- main loop ----
    for (int kc = 0; kc < NCHUNKS; kc++) {
        int bf = kc & 1;
        CP_WAIT1();
        __syncthreads();                       // buf bf fully staged & visible

        uint32_t wS = base + bf * 20480;
        uint32_t xS = wS + 10240;
#pragma unroll
        for (int ks = 0; ks < 2; ks++) {
            uint32_t a[4][4], bb[2][4];
#pragma unroll
            for (int mi = 0; mi < 4; mi++)
                LDMATRIX_X4(a[mi], wS + aoff + ks * 32 + mi * 16 * LDR);
#pragma unroll
            for (int nf = 0; nf < 2; nf++)
                LDMATRIX_X4(bb[nf], xS + boff + ks * 32 + nf * 16 * LDR);
#pragma unroll
            for (int mi = 0; mi < 4; mi++)
#pragma unroll
                for (int ni = 0; ni < 4; ni++)
                    MMA16816(acc[mi * 4 + ni], a[mi],
                             bb[ni >> 1][(ni & 1) * 2], bb[ni >> 1][(ni & 1) * 2 + 1]);
        }
        __syncthreads();                       // all warps done reading buf bf
        if (kc + 2 < NCHUNKS) stage(kc + 2, bf);
        CP_COMMIT();                           // keep group count uniform
    }

    // ---- epilogue: accums -> smem -> fused coalesced store ----
    {
        float* Ds = (float*)abase;
        int g = lane >> 2, t4 = lane & 3;
#pragma unroll
        for (int mi = 0; mi < 4; mi++)
#pragma unroll
            for (int ni = 0; ni < 4; ni++) {
                int row0 = moff + mi * 16 + g;
                int col = noff + ni * 8 + t4 * 2;
                float* ap = acc[mi * 4 + ni];
                *(float2*)&Ds[row0 * 132 + col]       = make_float2(ap[0], ap[1]);
                *(float2*)&Ds[(row0 + 8) * 132 + col] = make_float2(ap[2], ap[3]);
            }
        __syncthreads();

#pragma unroll 4
        for (int it = 0; it < 64; it++) {
            int pi = wid * 64 + it;
            int r2 = pi >> 2;            // o local
            int y = pi & 3;              // y local
            int o = obase + r2;
            float a = Ds[r2 * 132 + y * 32 + lane];
            float dv = g_d[b * 512 + o];
            float bv = bias[o];
            int oy = 2 * (ybase4 + y) + py;
            int ox = 2 * lane + px;
            float v = a * dv + bv + noise[b * 4096 + oy * 64 + ox];
            v = (v >= 0.f) ? v : 0.2f * v;
            out[((size_t)(b * 512 + o) << 12) + oy * 64 + ox] = v;
        }
    }
}

// ---------------------------------------------------------------------------
extern "C" void kernel_launch(void* const* d_in, const int* in_sizes, int n_in,
                              void* d_out, int out_size) {
    const float* x      = (const float*)d_in[0];
    const float* style  = (const float*)d_in[1];
    const float* noise  = (const float*)d_in[2];
    const float* conv_w = (const float*)d_in[3];
    const float* fc_w   = (const float*)d_in[4];
    const float* fc_b   = (const float*)d_in[5];
    const float* bias   = (const float*)d_in[6];
    float* out = (float*)d_out;

    cudaFuncSetAttribute(k_mma, cudaFuncAttributeMaxDynamicSharedMemorySize, SMEM_REQ);

    k_style<<<8, 512>>>(style, fc_w, fc_b);
    k_weff<<<1024, 256>>>(conv_w);
    k_demod<<<dim3(2, 8), 256>>>();
    k_xsplit<<<4096, 256>>>(x);
    k_mma<<<dim3(8, 4, 32), 256, SMEM_REQ>>>(noise, bias, out);
}

// round 9
// speedup vs baseline: 4.5386x; 1.0795x over previous
#include <cuda_runtime.h>
#include <cuda_fp16.h>
#include <cstdint>

// Problem constants
#define BB 8
#define CC 512
#define OO 512
#define KTOT 2048          // CC * 4 taps
#define KC 32              // K per chunk
#define NCHUNKS 64         // KTOT / KC
#define LDR 80             // smem row stride (bytes): 64B data + 16B pad

// Scratch (no allocation allowed -> device globals)
__device__ float g_smod[BB * CC];                    // 1 + style @ fc_w^T + fc_b
__device__ float g_d[BB * OO];                       // demod scale
__device__ float g_w2t[CC * OO];                     // sum_k conv_w^2, [c][o]
__device__ __align__(16) __half g_wh[4 * OO * KTOT]; // [p][o][k] fp16 parity weights
__device__ __align__(16) __half g_xs[BB * CC * 1024];// fp16(x * smod) [b][c][pix]

// ---------------------------------------------------------------------------
__device__ __forceinline__ uint32_t smem_u32(const void* p) {
    uint32_t a;
    asm("{ .reg .u64 t; cvta.to.shared.u64 t, %1; cvt.u32.u64 %0, t; }"
        : "=r"(a) : "l"(p));
    return a;
}
#define CP_ASYNC16(dst, src) \
    asm volatile("cp.async.cg.shared.global [%0], [%1], 16;\n" \
                 :: "r"(dst), "l"(__cvta_generic_to_global(src)))
#define CP_COMMIT()  asm volatile("cp.async.commit_group;\n" ::: "memory")
#define CP_WAIT0()   asm volatile("cp.async.wait_group 0;\n" ::: "memory")

#define LDMATRIX_X4(r, addr) \
    asm volatile("ldmatrix.sync.aligned.m8n8.x4.shared.b16 {%0,%1,%2,%3}, [%4];\n" \
                 : "=r"((r)[0]), "=r"((r)[1]), "=r"((r)[2]), "=r"((r)[3]) : "r"(addr))

#define MMA16816(d, a, b0v, b1v) \
    asm volatile("mma.sync.aligned.m16n8k16.row.col.f32.f16.f16.f32 " \
                 "{%0,%1,%2,%3},{%4,%5,%6,%7},{%8,%9},{%0,%1,%2,%3};\n" \
                 : "+f"((d)[0]), "+f"((d)[1]), "+f"((d)[2]), "+f"((d)[3]) \
                 : "r"((a)[0]), "r"((a)[1]), "r"((a)[2]), "r"((a)[3]), \
                   "r"(b0v), "r"(b1v))

// ---------------------------------------------------------------------------
// s[b][c] = 1 + fc_b[c] + sum_k style[b][k] * fc_w[c][k]
__global__ void k_style(const float* __restrict__ style,
                        const float* __restrict__ fc_w,
                        const float* __restrict__ fc_b) {
    __shared__ float ss[512];
    int b = blockIdx.x;
    int c = threadIdx.x;
    ss[c] = style[b * 512 + c];
    __syncthreads();
    const float4* wrow = (const float4*)(fc_w + (size_t)c * 512);
    float acc = 0.f;
#pragma unroll 4
    for (int k = 0; k < 128; k++) {
        float4 w4 = wrow[k];
        acc += w4.x * ss[4 * k + 0] + w4.y * ss[4 * k + 1]
             + w4.z * ss[4 * k + 2] + w4.w * ss[4 * k + 3];
    }
    g_smod[b * 512 + c] = acc + fc_b[c] + 1.0f;
}

// ---------------------------------------------------------------------------
// Per (o,c): W2^T and 4-parity combined 2x2 stencil weights (fp16).
// Layout g_wh: [p][o][k], k = c*4 + j*2 + i.
__global__ void k_weff(const float* __restrict__ conv_w) {
    int t = blockIdx.x * 256 + threadIdx.x;   // 262144 threads
    int o = t & 511;
    int c = t >> 9;
    const float* wp = conv_w + ((size_t)o * 512 + c) * 9;
    float w[9];
    float s2 = 0.f;
#pragma unroll
    for (int q = 0; q < 9; q++) { w[q] = wp[q]; s2 += w[q] * w[q]; }
    g_w2t[c * 512 + o] = s2;

#pragma unroll
    for (int py = 0; py < 2; py++) {
        float r0[3], r1[3];
#pragma unroll
        for (int kx = 0; kx < 3; kx++) {
            r0[kx] = (py == 0) ? w[kx]                 : w[kx] + w[3 + kx];
            r1[kx] = (py == 0) ? w[3 + kx] + w[6 + kx] : w[6 + kx];
        }
#pragma unroll
        for (int px = 0; px < 2; px++) {
            float v[4];
            v[0] = (px == 0) ? r0[0] : r0[0] + r0[1];
            v[1] = (px == 0) ? r0[1] + r0[2] : r0[2];
            v[2] = (px == 0) ? r1[0] : r1[0] + r1[1];
            v[3] = (px == 0) ? r1[1] + r1[2] : r1[2];
            int p = py * 2 + px;
            size_t kb = ((size_t)p * 512 + o) * 2048 + c * 4;
#pragma unroll
            for (int tap = 0; tap < 4; tap++)
                g_wh[kb + tap] = __float2half_rn(v[tap]);
        }
    }
}

// ---------------------------------------------------------------------------
// d[b][o] = rsqrt( sum_c smod[b][c]^2 * W2[o][c] + 1e-8 )
__global__ void k_demod() {
    __shared__ float s2[512];
    int b = blockIdx.y;
    int o = blockIdx.x * 256 + threadIdx.x;
    {
        float a = g_smod[b * 512 + threadIdx.x];
        float bv = g_smod[b * 512 + threadIdx.x + 256];
        s2[threadIdx.x] = a * a;
        s2[threadIdx.x + 256] = bv * bv;
    }
    __syncthreads();
    float acc = 1e-8f;
#pragma unroll 4
    for (int c = 0; c < 512; c++)
        acc += s2[c] * g_w2t[c * 512 + o];
    g_d[b * 512 + o] = rsqrtf(acc);
}

// ---------------------------------------------------------------------------
// xs[b][c][pix] = fp16( x[b][c][pix] * smod[b][c] ), float4-vectorized
__global__ void k_xsplit(const float* __restrict__ x) {
    int i = blockIdx.x * 256 + threadIdx.x;      // 1,048,576 threads
    int e0 = i * 4;
    int b = e0 >> 19;
    int c = (e0 >> 10) & 511;
    float s = g_smod[b * 512 + c];
    float4 v = *(const float4*)(x + e0);
    __half2 h0 = __floats2half2_rn(v.x * s, v.y * s);
    __half2 h1 = __floats2half2_rn(v.z * s, v.w * s);
    uint2 pk;
    pk.x = *(uint32_t*)&h0;
    pk.y = *(uint32_t*)&h1;
    *(uint2*)((char*)g_xs + (size_t)e0 * 2) = pk;
}

// ---------------------------------------------------------------------------
// Tensor-core implicit-GEMM conv via mma.sync (fp16 in, fp32 acc):
// per (b,p): D[o][n] = sum_k Weff[o][k] * Xg[n][k]
// CTA tile 128o x 128n, KC=32 double-buffered.
// Software pipeline: gather LDGs for chunk kc+1 issue BEFORE the MMAs of
// chunk kc (latency hidden), packed & stored to the next buffer after the
// MMAs; one __syncthreads per chunk.
// smem: buf0 W@0 X@10240, buf1 W@20480 X@30720; epilogue Ds[128][132] @0.
#define SMEM_REQ 67584

__global__ void __launch_bounds__(256, 2) k_mma(const float* __restrict__ noise,
                                                const float* __restrict__ bias,
                                                float* __restrict__ out) {
    extern __shared__ __align__(16) char smem_raw[];
    char* abase = smem_raw;
    uint32_t base = smem_u32(smem_raw);

    const int tid = threadIdx.x;
    const int wid = tid >> 5;
    const int lane = tid & 31;

    int bz = blockIdx.z;
    int b = bz >> 2, p = bz & 3;
    int py = p >> 1, px = p & 1;
    int obase = blockIdx.y * 128;
    int ybase4 = blockIdx.x * 4;

    // ---- gather thread constants ----
    const int nn = tid & 127;        // X-tile row (n local)
    const int khalf = tid >> 7;      // 0/1
    int yb = ybase4 + (nn >> 5);
    int xb = nn & 31;
    int offt[4];
    unsigned vt[4];
#pragma unroll
    for (int j = 0; j < 2; j++)
#pragma unroll
        for (int i = 0; i < 2; i++) {
            int tap = j * 2 + i;
            int yy = yb + j - 1 + py;
            int xx = xb + i - 1 + px;
            vt[tap] = ((unsigned)yy < 32u) && ((unsigned)xx < 32u);
            offt[tap] = yy * 32 + xx;
        }
    const unsigned short* xbase16 =
        (const unsigned short*)g_xs + ((size_t)b << 19);   // [c][pix]

    // ---- W loader constants ----
    const int wrow = tid >> 2;       // 0..63 base row (2 rows per thread)
    const int wseg = tid & 3;
    const __half* gw = g_wh + ((size_t)(p * 512 + obase)) * 2048;

    // ---- warp tile constants ----
    const int moff = (wid & 1) * 64;
    const int noff = (wid >> 1) * 32;
    const uint32_t aoff = (uint32_t)((moff + (lane & 15)) * LDR + ((lane >> 4) * 8) * 2);
    const uint32_t boff = (uint32_t)((noff + (lane & 7) + ((lane >> 4) << 3)) * LDR
                                     + (((lane >> 3) & 1) * 8) * 2);

    float acc[16][4];
#pragma unroll
    for (int q = 0; q < 16; q++)
#pragma unroll
        for (int r = 0; r < 4; r++) acc[q][r] = 0.f;

    // ---- prologue: stage chunk 0 into buf0 ----
    {
#pragma unroll
        for (int s = 0; s < 2; s++) {
            int row = wrow + 64 * s;
            CP_ASYNC16(base + row * LDR + wseg * 16,
                       gw + (size_t)row * 2048 + wseg * 8);
        }
        CP_COMMIT();
        char* xdst = abase + 10240;
#pragma unroll
        for (int q = 0; q < 4; q++) {
            int cl = khalf + 2 * q;
            const unsigned short* xc = xbase16 + ((size_t)cl << 10);
            unsigned u0 = vt[0] ? (unsigned)xc[offt[0]] : 0u;
            unsigned u1 = vt[1] ? (unsigned)xc[offt[1]] : 0u;
            unsigned u2 = vt[2] ? (unsigned)xc[offt[2]] : 0u;
            unsigned u3 = vt[3] ? (unsigned)xc[offt[3]] : 0u;
            *(uint2*)(xdst + nn * LDR + cl * 8) =
                make_uint2(u0 | (u1 << 16), u2 | (u3 << 16));
        }
        CP_WAIT0();
        __syncthreads();
    }

    // ---- main pipelined loop ----
    for (int kc = 0; kc < NCHUNKS; kc++) {
        int bf = kc & 1;
        int nb = bf ^ 1;
        bool have_next = (kc + 1 < NCHUNKS);

        // 1) issue next chunk's feeds early (latency overlapped with MMAs)
        uint2 gx[4];
        if (have_next) {
            int kn = kc + 1;
            uint32_t wdst = base + nb * 20480;
#pragma unroll
            for (int s = 0; s < 2; s++) {
                int row = wrow + 64 * s;
                CP_ASYNC16(wdst + row * LDR + wseg * 16,
                           gw + (size_t)row * 2048 + kn * 32 + wseg * 8);
            }
#pragma unroll
            for (int q = 0; q < 4; q++) {
                int cl = khalf + 2 * q;
                const unsigned short* xc = xbase16 + ((size_t)(kn * 8 + cl) << 10);
                unsigned u0 = vt[0] ? (unsigned)__ldg(xc + offt[0]) : 0u;
                unsigned u1 = vt[1] ? (unsigned)__ldg(xc + offt[1]) : 0u;
                unsigned u2 = vt[2] ? (unsigned)__ldg(xc + offt[2]) : 0u;
                unsigned u3 = vt[3] ? (unsigned)__ldg(xc + offt[3]) : 0u;
                gx[q] = make_uint2(u0 | (u1 << 16), u2 | (u3 << 16));
            }
        }
        CP_COMMIT();

        // 2) MMAs on current buffer
        uint32_t wS = base + bf * 20480;
        uint32_t xS = wS + 10240;
#pragma unroll
        for (int ks = 0; ks < 2; ks++) {
            uint32_t a[4][4], bb[2][4];
#pragma unroll
            for (int mi = 0; mi < 4; mi++)
                LDMATRIX_X4(a[mi], wS + aoff + ks * 32 + mi * 16 * LDR);
#pragma unroll
            for (int nf = 0; nf < 2; nf++)
                LDMATRIX_X4(bb[nf], xS + boff + ks * 32 + nf * 16 * LDR);
#pragma unroll
            for (int mi = 0; mi < 4; mi++)
#pragma unroll
                for (int ni = 0; ni < 4; ni++)
                    MMA16816(acc[mi * 4 + ni], a[mi],
                             bb[ni >> 1][(ni & 1) * 2], bb[ni >> 1][(ni & 1) * 2 + 1]);
        }

        // 3) land the gathered X into the next buffer, wait W, one barrier
        if (have_next) {
            char* xdst = abase + nb * 20480 + 10240;
#pragma unroll
            for (int q = 0; q < 4; q++) {
                int cl = khalf + 2 * q;
                *(uint2*)(xdst + nn * LDR + cl * 8) = gx[q];
            }
        }
        CP_WAIT0();
        __syncthreads();
    }

    // ---- epilogue: accums -> smem -> fused coalesced store ----
    {
        float* Ds = (float*)abase;
        int g = lane >> 2, t4 = lane & 3;
#pragma unroll
        for (int mi = 0; mi < 4; mi++)
#pragma unroll
            for (int ni = 0; ni < 4; ni++) {
                int row0 = moff + mi * 16 + g;
                int col = noff + ni * 8 + t4 * 2;
                float* ap = acc[mi * 4 + ni];
                *(float2*)&Ds[row0 * 132 + col]       = make_float2(ap[0], ap[1]);
                *(float2*)&Ds[(row0 + 8) * 132 + col] = make_float2(ap[2], ap[3]);
            }
        __syncthreads();

#pragma unroll 4
        for (int it = 0; it < 64; it++) {
            int pi = wid * 64 + it;
            int r2 = pi >> 2;            // o local
            int y = pi & 3;              // y local
            int o = obase + r2;
            float a = Ds[r2 * 132 + y * 32 + lane];
            float dv = g_d[b * 512 + o];
            float bv = bias[o];
            int oy = 2 * (ybase4 + y) + py;
            int ox = 2 * lane + px;
            float v = a * dv + bv + noise[b * 4096 + oy * 64 + ox];
            v = (v >= 0.f) ? v : 0.2f * v;
            out[((size_t)(b * 512 + o) << 12) + oy * 64 + ox] = v;
        }
    }
}

// ---------------------------------------------------------------------------
extern "C" void kernel_launch(void* const* d_in, const int* in_sizes, int n_in,
                              void* d_out, int out_size) {
    const float* x      = (const float*)d_in[0];
    const float* style  = (const float*)d_in[1];
    const float* noise  = (const float*)d_in[2];
    const float* conv_w = (const float*)d_in[3];
    const float* fc_w   = (const float*)d_in[4];
    const float* fc_b   = (const float*)d_in[5];
    const float* bias   = (const float*)d_in[6];
    float* out = (float*)d_out;

    cudaFuncSetAttribute(k_mma, cudaFuncAttributeMaxDynamicSharedMemorySize, SMEM_REQ);

    k_style<<<8, 512>>>(style, fc_w, fc_b);
    k_weff<<<1024, 256>>>(conv_w);
    k_demod<<<dim3(2, 8), 256>>>();
    k_xsplit<<<4096, 256>>>(x);
    k_mma<<<dim3(8, 4, 32), 256, SMEM_REQ>>>(noise, bias, out);
}